// round 1
// baseline (speedup 1.0000x reference)
#include <cuda_runtime.h>
#include <cstdint>

// Problem constants
#define M_TOT   138240      // B_*nW*N = 15*64*144
#define C_DIM   192
#define NHEAD   6
#define LDIM    32
#define NTOK    144
#define NWIN    64
#define NB      15
#define QKV_N   576

// Scratch (device globals; no allocations allowed)
__device__ float g_qkv[(size_t)M_TOT * QKV_N];                    // 318 MB
__device__ float g_bias[(size_t)NHEAD * NWIN * NTOK * NTOK];      // 32 MB
__device__ float g_att[(size_t)M_TOT * C_DIM];                    // 106 MB

// ---------------------------------------------------------------------------
// Kernel 1: gather earth-position bias into [h][w][n][m] layout
//   epi(n,m) = 828*(z1+2*z2) + 23*(h1+6*h2) + (w1 - w2 + 11)
//   g_bias[h][w][n][m] = bias_table[epi*384 + w*6 + h]
// ---------------------------------------------------------------------------
__global__ void bias_gather_kernel(const float* __restrict__ table)
{
    int idx = blockIdx.x * blockDim.x + threadIdx.x;   // over n*m = 20736
    if (idx >= NTOK * NTOK) return;
    int m = idx % NTOK, n = idx / NTOK;
    int z1 = n / 72, h1 = (n / 12) % 6, w1 = n % 12;
    int z2 = m / 72, h2 = (m / 12) % 6, w2 = m % 12;
    int epi = (z1 + 2 * z2) * 828 + (h1 + 6 * h2) * 23 + (w1 - w2 + 11);
    const float* trow = table + (size_t)epi * (NWIN * NHEAD);
    #pragma unroll 4
    for (int wh = 0; wh < NWIN * NHEAD; wh++) {
        int w = wh / NHEAD, h = wh % NHEAD;
        g_bias[((size_t)(h * NWIN + w)) * (NTOK * NTOK) + idx] = trow[wh];
    }
}

// ---------------------------------------------------------------------------
// Kernel 2/4: C[M,N] = A[M,K] @ W[N,K]^T + bias[N]
// 128x64 block tile, BK=16, 256 threads, 8x4 microtile, float4 everywhere.
// M % 128 == 0, N % 64 == 0, K % 16 == 0 guaranteed by problem shapes.
// ---------------------------------------------------------------------------
__global__ __launch_bounds__(256) void gemm_bias_kernel(
    const float* __restrict__ A, const float* __restrict__ W,
    const float* __restrict__ bias, float* __restrict__ C,
    int M, int N, int K)
{
    __shared__ float As[16][128];
    __shared__ float Bs[16][64];

    const int tid = threadIdx.x;
    const int bm  = blockIdx.y * 128;
    const int bn  = blockIdx.x * 64;
    const int ty  = tid >> 4;     // 0..15 -> rows ty*8..+7
    const int tx  = tid & 15;     // 0..15 -> cols tx*4..+3

    float acc[8][4];
    #pragma unroll
    for (int i = 0; i < 8; i++)
        #pragma unroll
        for (int j = 0; j < 4; j++) acc[i][j] = 0.f;

    for (int k0 = 0; k0 < K; k0 += 16) {
        // A tile: 128x16 = 512 float4 loads, 2 per thread
        #pragma unroll
        for (int i = 0; i < 2; i++) {
            int idx = tid + i * 256;
            int m   = idx >> 2;
            int kk  = (idx & 3) << 2;
            const float4 v = *(const float4*)(A + (size_t)(bm + m) * K + k0 + kk);
            As[kk + 0][m] = v.x; As[kk + 1][m] = v.y;
            As[kk + 2][m] = v.z; As[kk + 3][m] = v.w;
        }
        // W tile: 64x16 = 256 float4 loads, 1 per thread
        {
            int n  = tid >> 2;
            int kk = (tid & 3) << 2;
            const float4 v = *(const float4*)(W + (size_t)(bn + n) * K + k0 + kk);
            Bs[kk + 0][n] = v.x; Bs[kk + 1][n] = v.y;
            Bs[kk + 2][n] = v.z; Bs[kk + 3][n] = v.w;
        }
        __syncthreads();

        #pragma unroll
        for (int kk = 0; kk < 16; kk++) {
            float4 a0 = *(const float4*)&As[kk][ty * 8];
            float4 a1 = *(const float4*)&As[kk][ty * 8 + 4];
            float4 b0 = *(const float4*)&Bs[kk][tx * 4];
            float a[8] = {a0.x, a0.y, a0.z, a0.w, a1.x, a1.y, a1.z, a1.w};
            float b[4] = {b0.x, b0.y, b0.z, b0.w};
            #pragma unroll
            for (int i = 0; i < 8; i++)
                #pragma unroll
                for (int j = 0; j < 4; j++) acc[i][j] += a[i] * b[j];
        }
        __syncthreads();
    }

    const float4 bv = *(const float4*)(bias + bn + tx * 4);
    #pragma unroll
    for (int i = 0; i < 8; i++) {
        int m = bm + ty * 8 + i;
        float4 out;
        out.x = acc[i][0] + bv.x;
        out.y = acc[i][1] + bv.y;
        out.z = acc[i][2] + bv.z;
        out.w = acc[i][3] + bv.w;
        *(float4*)(C + (size_t)m * N + bn + tx * 4) = out;
    }
}

// ---------------------------------------------------------------------------
// Kernel 3: fused attention per (b_, h, w) block.
//   S = scale * Q K^T + bias + mask ; P = softmax(S) ; O = P V
// 256 threads. S kept in smem [144][145] (pad 145 -> conflict-free rows).
// ---------------------------------------------------------------------------
#define AT_THREADS 256
#define SPAD 145
#define ATTN_SMEM_FLOATS (NTOK * SPAD + 2 * 32 * SPAD + NTOK * 32 + NTOK)
#define ATTN_SMEM_BYTES  (ATTN_SMEM_FLOATS * 4)

__global__ __launch_bounds__(AT_THREADS, 1) void attn_kernel(
    const float* __restrict__ mask)
{
    const int w  = blockIdx.x & 63;
    const int hh = (blockIdx.x >> 6) % NHEAD;
    const int b_ = blockIdx.x / (NWIN * NHEAD);

    extern __shared__ float sm[];
    float* Ss    = sm;                       // [144][145]
    float* Qs    = Ss + NTOK * SPAD;         // [32][145]  (transposed: [l][n])
    float* Ks    = Qs + 32 * SPAD;           // [32][145]  (transposed: [l][m])
    float* Vs    = Ks + 32 * SPAD;           // [144][32]
    float* inv_s = Vs + NTOK * 32;           // [144]

    const int tid     = threadIdx.x;
    const int rowbase = (b_ * NWIN + w) * NTOK;

    // Stage Q,K (transposed) and V into smem. Coalesced float4 global loads.
    for (int i = tid; i < NTOK * 8; i += AT_THREADS) {
        int n  = i >> 3;
        int l4 = (i & 7) << 2;
        const float* base = g_qkv + (size_t)(rowbase + n) * QKV_N + hh * LDIM;
        float4 q4 = *(const float4*)(base + l4);
        float4 k4 = *(const float4*)(base + 192 + l4);
        float4 v4 = *(const float4*)(base + 384 + l4);
        Qs[(l4 + 0) * SPAD + n] = q4.x; Qs[(l4 + 1) * SPAD + n] = q4.y;
        Qs[(l4 + 2) * SPAD + n] = q4.z; Qs[(l4 + 3) * SPAD + n] = q4.w;
        Ks[(l4 + 0) * SPAD + n] = k4.x; Ks[(l4 + 1) * SPAD + n] = k4.y;
        Ks[(l4 + 2) * SPAD + n] = k4.z; Ks[(l4 + 3) * SPAD + n] = k4.w;
        *(float4*)(Vs + n * 32 + l4) = v4;
    }
    __syncthreads();

    // GEMM1: S[n][m] = sum_l Qs[l][n] * Ks[l][m]; 9x9 microtile over 16x16 threads
    const int ty = tid >> 4, tx = tid & 15;
    const int r0 = ty * 9,  c0 = tx * 9;
    float acc[9][9];
    #pragma unroll
    for (int i = 0; i < 9; i++)
        #pragma unroll
        for (int j = 0; j < 9; j++) acc[i][j] = 0.f;

    #pragma unroll 4
    for (int l = 0; l < 32; l++) {
        float a[9], b[9];
        #pragma unroll
        for (int i = 0; i < 9; i++) a[i] = Qs[l * SPAD + r0 + i];
        #pragma unroll
        for (int j = 0; j < 9; j++) b[j] = Ks[l * SPAD + c0 + j];
        #pragma unroll
        for (int i = 0; i < 9; i++)
            #pragma unroll
            for (int j = 0; j < 9; j++) acc[i][j] += a[i] * b[j];
    }
    const float scale = 0.17677669529663687f;   // 32^-0.5
    #pragma unroll
    for (int i = 0; i < 9; i++)
        #pragma unroll
        for (int j = 0; j < 9; j++)
            Ss[(r0 + i) * SPAD + c0 + j] = acc[i][j] * scale;
    __syncthreads();

    // Add bias + mask (coalesced global streams)
    {
        const float* bslab = g_bias + (size_t)(hh * NWIN + w) * (NTOK * NTOK);
        const float* mslab = mask   + (size_t)(b_ * NWIN + w) * (NTOK * NTOK);
        for (int i = tid; i < NTOK * NTOK; i += AT_THREADS) {
            int n = i / NTOK;
            int m = i - n * NTOK;
            Ss[n * SPAD + m] += bslab[i] + mslab[i];
        }
    }
    __syncthreads();

    // Row softmax (one thread per row; pad-145 rows are bank-conflict-free)
    if (tid < NTOK) {
        float* row = Ss + tid * SPAD;
        float mx = -1e30f;
        #pragma unroll 4
        for (int m = 0; m < NTOK; m++) mx = fmaxf(mx, row[m]);
        float sum = 0.f;
        #pragma unroll 4
        for (int m = 0; m < NTOK; m++) {
            float e = __expf(row[m] - mx);
            row[m] = e;
            sum += e;
        }
        inv_s[tid] = 1.0f / sum;
    }
    __syncthreads();

    // GEMM2: O[n][l] = sum_m P[n][m] * V[m][l]; 9x2 microtile
    const int l0 = tx * 2;
    float acc2[9][2];
    #pragma unroll
    for (int i = 0; i < 9; i++) { acc2[i][0] = 0.f; acc2[i][1] = 0.f; }

    #pragma unroll 4
    for (int m = 0; m < NTOK; m++) {
        float v0 = Vs[m * 32 + l0];
        float v1 = Vs[m * 32 + l0 + 1];
        #pragma unroll
        for (int i = 0; i < 9; i++) {
            float p = Ss[(r0 + i) * SPAD + m];
            acc2[i][0] += p * v0;
            acc2[i][1] += p * v1;
        }
    }
    #pragma unroll
    for (int i = 0; i < 9; i++) {
        float inv = inv_s[r0 + i];
        float2 o;
        o.x = acc2[i][0] * inv;
        o.y = acc2[i][1] * inv;
        *(float2*)(g_att + (size_t)(rowbase + r0 + i) * C_DIM + hh * LDIM + l0) = o;
    }
}

// ---------------------------------------------------------------------------
// Launch
// ---------------------------------------------------------------------------
extern "C" void kernel_launch(void* const* d_in, const int* in_sizes, int n_in,
                              void* d_out, int out_size)
{
    const float* x      = (const float*)d_in[0];
    const float* mask   = (const float*)d_in[1];
    const float* qkv_w  = (const float*)d_in[2];
    const float* qkv_b  = (const float*)d_in[3];
    const float* proj_w = (const float*)d_in[4];
    const float* proj_b = (const float*)d_in[5];
    const float* btab   = (const float*)d_in[6];
    float* out = (float*)d_out;

    float *qkv_p, *att_p;
    cudaGetSymbolAddress((void**)&qkv_p, g_qkv);
    cudaGetSymbolAddress((void**)&att_p, g_att);

    cudaFuncSetAttribute(attn_kernel,
                         cudaFuncAttributeMaxDynamicSharedMemorySize,
                         ATTN_SMEM_BYTES);

    // 1) bias gather (independent of QKV GEMM, tiny)
    bias_gather_kernel<<<(NTOK * NTOK + 255) / 256, 256>>>(btab);

    // 2) QKV projection: [138240,192] @ [576,192]^T + b
    gemm_bias_kernel<<<dim3(QKV_N / 64, M_TOT / 128), 256>>>(
        x, qkv_w, qkv_b, qkv_p, M_TOT, QKV_N, C_DIM);

    // 3) fused attention, one block per (b_, h, w)
    attn_kernel<<<NB * NHEAD * NWIN, AT_THREADS, ATTN_SMEM_BYTES>>>(mask);

    // 4) output projection: [138240,192] @ [192,192]^T + b
    gemm_bias_kernel<<<dim3(C_DIM / 64, M_TOT / 128), 256>>>(
        att_p, proj_w, proj_b, out, M_TOT, C_DIM, C_DIM);
}

// round 2
// speedup vs baseline: 1.0055x; 1.0055x over previous
#include <cuda_runtime.h>
#include <cstdint>

// Problem constants
#define M_TOT   138240      // B_*nW*N = 15*64*144
#define C_DIM   192
#define NHEAD   6
#define LDIM    32
#define NTOK    144
#define NWIN    64
#define NB      15
#define QKV_N   576

// Scratch (device globals; no allocations allowed)
__device__ float g_qkv[(size_t)M_TOT * QKV_N];                    // 318 MB
__device__ float g_bias[(size_t)NHEAD * NWIN * NTOK * NTOK];      // 32 MB
__device__ float g_att[(size_t)M_TOT * C_DIM];                    // 106 MB

// ---------------------------------------------------------------------------
// Kernel 1: gather earth-position bias into [h][w][n][m] layout
//   epi(n,m) = 828*(z1+2*z2) + 23*(h1+6*h2) + (w1 - w2 + 11)
// ---------------------------------------------------------------------------
__global__ void bias_gather_kernel(const float* __restrict__ table)
{
    int idx = blockIdx.x * blockDim.x + threadIdx.x;   // over n*m = 20736
    if (idx >= NTOK * NTOK) return;
    int m = idx % NTOK, n = idx / NTOK;
    int z1 = n / 72, h1 = (n / 12) % 6, w1 = n % 12;
    int z2 = m / 72, h2 = (m / 12) % 6, w2 = m % 12;
    int epi = (z1 + 2 * z2) * 828 + (h1 + 6 * h2) * 23 + (w1 - w2 + 11);
    const float* trow = table + (size_t)epi * (NWIN * NHEAD);
    #pragma unroll 4
    for (int wh = 0; wh < NWIN * NHEAD; wh++) {
        int w = wh / NHEAD, h = wh % NHEAD;
        g_bias[((size_t)(h * NWIN + w)) * (NTOK * NTOK) + idx] = trow[wh];
    }
}

// ---------------------------------------------------------------------------
// Kernel 2/4: C[M,N] = A[M,K] @ W[N,K]^T + bias[N]
// 128x64 block tile, BK=16, 128 threads, 8x8 microtile, double-buffered smem.
// ---------------------------------------------------------------------------
__global__ __launch_bounds__(128, 4) void gemm_bias_kernel(
    const float* __restrict__ A, const float* __restrict__ W,
    const float* __restrict__ bias, float* __restrict__ C,
    int M, int N, int K)
{
    __shared__ float As[2][16][128];
    __shared__ float Bs[2][16][64];

    const int tid = threadIdx.x;
    const int bm  = blockIdx.y * 128;
    const int bn  = blockIdx.x * 64;
    const int ty  = tid >> 3;     // 0..15 -> rows ty*8..+7
    const int tx  = tid & 7;      // 0..7  -> cols tx*8..+7

    float acc[8][8];
    #pragma unroll
    for (int i = 0; i < 8; i++)
        #pragma unroll
        for (int j = 0; j < 8; j++) acc[i][j] = 0.f;

    // Per-thread staging coords (A: 4 float4, B: 2 float4)
    float4 pa[4], pb[2];

    const int nk = K >> 4;

    // Prefetch k-block 0 into registers
    #pragma unroll
    for (int i = 0; i < 4; i++) {
        int idx = tid + i * 128;
        pa[i] = *(const float4*)(A + (size_t)(bm + (idx >> 2)) * K + ((idx & 3) << 2));
    }
    #pragma unroll
    for (int i = 0; i < 2; i++) {
        int idx = tid + i * 128;
        pb[i] = *(const float4*)(W + (size_t)(bn + (idx >> 2)) * K + ((idx & 3) << 2));
    }
    // Store to buffer 0
    #pragma unroll
    for (int i = 0; i < 4; i++) {
        int idx = tid + i * 128;
        int m = idx >> 2, kk = (idx & 3) << 2;
        As[0][kk + 0][m] = pa[i].x; As[0][kk + 1][m] = pa[i].y;
        As[0][kk + 2][m] = pa[i].z; As[0][kk + 3][m] = pa[i].w;
    }
    #pragma unroll
    for (int i = 0; i < 2; i++) {
        int idx = tid + i * 128;
        int n = idx >> 2, kk = (idx & 3) << 2;
        Bs[0][kk + 0][n] = pb[i].x; Bs[0][kk + 1][n] = pb[i].y;
        Bs[0][kk + 2][n] = pb[i].z; Bs[0][kk + 3][n] = pb[i].w;
    }
    __syncthreads();

    for (int kb = 0; kb < nk; kb++) {
        const int cur = kb & 1;
        const int k1  = (kb + 1) << 4;
        // Prefetch next k-block while computing current
        if (kb + 1 < nk) {
            #pragma unroll
            for (int i = 0; i < 4; i++) {
                int idx = tid + i * 128;
                pa[i] = *(const float4*)(A + (size_t)(bm + (idx >> 2)) * K + k1 + ((idx & 3) << 2));
            }
            #pragma unroll
            for (int i = 0; i < 2; i++) {
                int idx = tid + i * 128;
                pb[i] = *(const float4*)(W + (size_t)(bn + (idx >> 2)) * K + k1 + ((idx & 3) << 2));
            }
        }

        #pragma unroll
        for (int kk = 0; kk < 16; kk++) {
            float4 a0 = *(const float4*)&As[cur][kk][ty * 8];
            float4 a1 = *(const float4*)&As[cur][kk][ty * 8 + 4];
            float4 b0 = *(const float4*)&Bs[cur][kk][tx * 8];
            float4 b1 = *(const float4*)&Bs[cur][kk][tx * 8 + 4];
            float a[8] = {a0.x, a0.y, a0.z, a0.w, a1.x, a1.y, a1.z, a1.w};
            float b[8] = {b0.x, b0.y, b0.z, b0.w, b1.x, b1.y, b1.z, b1.w};
            #pragma unroll
            for (int i = 0; i < 8; i++)
                #pragma unroll
                for (int j = 0; j < 8; j++) acc[i][j] += a[i] * b[j];
        }

        if (kb + 1 < nk) {
            const int nxt = cur ^ 1;
            #pragma unroll
            for (int i = 0; i < 4; i++) {
                int idx = tid + i * 128;
                int m = idx >> 2, kk = (idx & 3) << 2;
                As[nxt][kk + 0][m] = pa[i].x; As[nxt][kk + 1][m] = pa[i].y;
                As[nxt][kk + 2][m] = pa[i].z; As[nxt][kk + 3][m] = pa[i].w;
            }
            #pragma unroll
            for (int i = 0; i < 2; i++) {
                int idx = tid + i * 128;
                int n = idx >> 2, kk = (idx & 3) << 2;
                Bs[nxt][kk + 0][n] = pb[i].x; Bs[nxt][kk + 1][n] = pb[i].y;
                Bs[nxt][kk + 2][n] = pb[i].z; Bs[nxt][kk + 3][n] = pb[i].w;
            }
            __syncthreads();
        }
    }

    const float4 bv0 = *(const float4*)(bias + bn + tx * 8);
    const float4 bv1 = *(const float4*)(bias + bn + tx * 8 + 4);
    #pragma unroll
    for (int i = 0; i < 8; i++) {
        int m = bm + ty * 8 + i;
        float4 o0, o1;
        o0.x = acc[i][0] + bv0.x; o0.y = acc[i][1] + bv0.y;
        o0.z = acc[i][2] + bv0.z; o0.w = acc[i][3] + bv0.w;
        o1.x = acc[i][4] + bv1.x; o1.y = acc[i][5] + bv1.y;
        o1.z = acc[i][6] + bv1.z; o1.w = acc[i][7] + bv1.w;
        *(float4*)(C + (size_t)m * N + bn + tx * 8)     = o0;
        *(float4*)(C + (size_t)m * N + bn + tx * 8 + 4) = o1;
    }
}

// ---------------------------------------------------------------------------
// Kernel 3: fused attention per (b_, h, w) block.
//   S = scale * Q K^T + bias + mask ; P = softmax(S) ; O = P V
// 576 threads (18 warps). S in smem [144][148].
// GEMM1: 24x24 grid of 6x6 microtiles. Softmax: 4 threads/row + shuffle.
// GEMM2: thread = (row, 8-wide l-group), float4 V loads.
// ---------------------------------------------------------------------------
#define AT_THREADS 576
#define SPAD 148
#define ATTN_SMEM_FLOATS (NTOK * SPAD + 2 * 32 * SPAD + NTOK * 32 + NTOK)
#define ATTN_SMEM_BYTES  (ATTN_SMEM_FLOATS * 4)

__global__ __launch_bounds__(AT_THREADS, 1) void attn_kernel(
    const float* __restrict__ mask)
{
    const int w  = blockIdx.x & 63;
    const int hh = (blockIdx.x >> 6) % NHEAD;
    const int b_ = blockIdx.x / (NWIN * NHEAD);

    extern __shared__ float sm[];
    float* Ss    = sm;                       // [144][148]
    float* Qs    = Ss + NTOK * SPAD;         // [32][148]  (transposed: [l][n])
    float* Ks    = Qs + 32 * SPAD;           // [32][148]  (transposed: [l][m])
    float* Vs    = Ks + 32 * SPAD;           // [144][32]
    float* inv_s = Vs + NTOK * 32;           // [144]

    const int tid     = threadIdx.x;
    const int rowbase = (b_ * NWIN + w) * NTOK;

    // Stage Q,K (transposed) and V. 1152 float4 triplets / 576 threads = 2 each.
    #pragma unroll
    for (int it = 0; it < 2; it++) {
        int i  = tid + it * AT_THREADS;
        int n  = i >> 3;
        int l4 = (i & 7) << 2;
        const float* base = g_qkv + (size_t)(rowbase + n) * QKV_N + hh * LDIM;
        float4 q4 = *(const float4*)(base + l4);
        float4 k4 = *(const float4*)(base + 192 + l4);
        float4 v4 = *(const float4*)(base + 384 + l4);
        Qs[(l4 + 0) * SPAD + n] = q4.x; Qs[(l4 + 1) * SPAD + n] = q4.y;
        Qs[(l4 + 2) * SPAD + n] = q4.z; Qs[(l4 + 3) * SPAD + n] = q4.w;
        Ks[(l4 + 0) * SPAD + n] = k4.x; Ks[(l4 + 1) * SPAD + n] = k4.y;
        Ks[(l4 + 2) * SPAD + n] = k4.z; Ks[(l4 + 3) * SPAD + n] = k4.w;
        *(float4*)(Vs + n * 32 + l4) = v4;
    }
    __syncthreads();

    // GEMM1: S[n][m] = sum_l Qs[l][n] * Ks[l][m]; 6x6 microtile, 24x24 grid
    {
        const int ty = tid / 24, tx = tid % 24;
        const int r0 = ty * 6,  c0 = tx * 6;
        float acc[6][6];
        #pragma unroll
        for (int i = 0; i < 6; i++)
            #pragma unroll
            for (int j = 0; j < 6; j++) acc[i][j] = 0.f;

        #pragma unroll 4
        for (int l = 0; l < 32; l++) {
            float a[6], b[6];
            const float2* ap = (const float2*)(Qs + l * SPAD + r0);
            const float2* bp = (const float2*)(Ks + l * SPAD + c0);
            float2 t;
            t = ap[0]; a[0] = t.x; a[1] = t.y;
            t = ap[1]; a[2] = t.x; a[3] = t.y;
            t = ap[2]; a[4] = t.x; a[5] = t.y;
            t = bp[0]; b[0] = t.x; b[1] = t.y;
            t = bp[1]; b[2] = t.x; b[3] = t.y;
            t = bp[2]; b[4] = t.x; b[5] = t.y;
            #pragma unroll
            for (int i = 0; i < 6; i++)
                #pragma unroll
                for (int j = 0; j < 6; j++) acc[i][j] += a[i] * b[j];
        }
        const float scale = 0.17677669529663687f;   // 32^-0.5
        #pragma unroll
        for (int i = 0; i < 6; i++)
            #pragma unroll
            for (int j = 0; j < 6; j++)
                Ss[(r0 + i) * SPAD + c0 + j] = acc[i][j] * scale;
    }
    __syncthreads();

    // Add bias + mask (coalesced global streams). 20736/576 = 36 iters.
    {
        const float* bslab = g_bias + (size_t)(hh * NWIN + w) * (NTOK * NTOK);
        const float* mslab = mask   + (size_t)(b_ * NWIN + w) * (NTOK * NTOK);
        #pragma unroll 4
        for (int it = 0; it < 36; it++) {
            int i = tid + it * AT_THREADS;
            int n = i / NTOK;
            int m = i - n * NTOK;
            Ss[n * SPAD + m] += bslab[i] + mslab[i];
        }
    }
    __syncthreads();

    // Softmax: 4 threads per row (576 = 144*4), 36 cols each, shuffle-reduce.
    {
        const int r = tid >> 2, q = tid & 3;
        float* row = Ss + r * SPAD + q * 36;
        float mx = -1e30f;
        #pragma unroll 4
        for (int c = 0; c < 36; c++) mx = fmaxf(mx, row[c]);
        mx = fmaxf(mx, __shfl_xor_sync(0xffffffffu, mx, 1));
        mx = fmaxf(mx, __shfl_xor_sync(0xffffffffu, mx, 2));
        float sum = 0.f;
        #pragma unroll 4
        for (int c = 0; c < 36; c++) {
            float e = __expf(row[c] - mx);
            row[c] = e;
            sum += e;
        }
        sum += __shfl_xor_sync(0xffffffffu, sum, 1);
        sum += __shfl_xor_sync(0xffffffffu, sum, 2);
        if (q == 0) inv_s[r] = 1.0f / sum;
    }
    __syncthreads();

    // GEMM2: O[r][l] = sum_m P[r][m] * V[m][l]; thread = (row, 8-wide l-group)
    {
        const int r  = tid >> 2;
        const int l0 = (tid & 3) << 3;
        float acc2[8];
        #pragma unroll
        for (int j = 0; j < 8; j++) acc2[j] = 0.f;

        const float* srow = Ss + r * SPAD;
        #pragma unroll 4
        for (int m = 0; m < NTOK; m++) {
            float4 v0 = *(const float4*)(Vs + m * 32 + l0);
            float4 v1 = *(const float4*)(Vs + m * 32 + l0 + 4);
            float p = srow[m];
            acc2[0] += p * v0.x; acc2[1] += p * v0.y;
            acc2[2] += p * v0.z; acc2[3] += p * v0.w;
            acc2[4] += p * v1.x; acc2[5] += p * v1.y;
            acc2[6] += p * v1.z; acc2[7] += p * v1.w;
        }
        const float inv = inv_s[r];
        float4 o0, o1;
        o0.x = acc2[0] * inv; o0.y = acc2[1] * inv;
        o0.z = acc2[2] * inv; o0.w = acc2[3] * inv;
        o1.x = acc2[4] * inv; o1.y = acc2[5] * inv;
        o1.z = acc2[6] * inv; o1.w = acc2[7] * inv;
        float* obase = g_att + (size_t)(rowbase + r) * C_DIM + hh * LDIM + l0;
        *(float4*)(obase)     = o0;
        *(float4*)(obase + 4) = o1;
    }
}

// ---------------------------------------------------------------------------
// Launch
// ---------------------------------------------------------------------------
extern "C" void kernel_launch(void* const* d_in, const int* in_sizes, int n_in,
                              void* d_out, int out_size)
{
    const float* x      = (const float*)d_in[0];
    const float* mask   = (const float*)d_in[1];
    const float* qkv_w  = (const float*)d_in[2];
    const float* qkv_b  = (const float*)d_in[3];
    const float* proj_w = (const float*)d_in[4];
    const float* proj_b = (const float*)d_in[5];
    const float* btab   = (const float*)d_in[6];
    float* out = (float*)d_out;

    float *qkv_p, *att_p;
    cudaGetSymbolAddress((void**)&qkv_p, g_qkv);
    cudaGetSymbolAddress((void**)&att_p, g_att);

    cudaFuncSetAttribute(attn_kernel,
                         cudaFuncAttributeMaxDynamicSharedMemorySize,
                         ATTN_SMEM_BYTES);

    // 1) bias gather
    bias_gather_kernel<<<(NTOK * NTOK + 255) / 256, 256>>>(btab);

    // 2) QKV projection: [138240,192] @ [576,192]^T + b
    gemm_bias_kernel<<<dim3(QKV_N / 64, M_TOT / 128), 128>>>(
        x, qkv_w, qkv_b, qkv_p, M_TOT, QKV_N, C_DIM);

    // 3) fused attention, one block per (b_, h, w)
    attn_kernel<<<NB * NHEAD * NWIN, AT_THREADS, ATTN_SMEM_BYTES>>>(mask);

    // 4) output projection: [138240,192] @ [192,192]^T + b
    gemm_bias_kernel<<<dim3(C_DIM / 64, M_TOT / 128), 128>>>(
        att_p, proj_w, proj_b, out, M_TOT, C_DIM, C_DIM);
}

// round 5
// speedup vs baseline: 1.4572x; 1.4492x over previous
#include <cuda_runtime.h>
#include <cuda_bf16.h>
#include <cstdint>

// Problem constants
#define M_TOT   138240      // B_*nW*N = 15*64*144
#define C_DIM   192
#define NHEAD   6
#define LDIM    32
#define NTOK    144
#define NWIN    64
#define NB      15
#define QKV_N   576
#define KDIM    192

// Scratch (device globals; no allocations allowed)
__device__ float g_qkv[(size_t)M_TOT * QKV_N];                    // 318 MB
__device__ float g_bias[(size_t)NHEAD * NWIN * NTOK * NTOK];      // 32 MB
__device__ __nv_bfloat16 g_xhi[(size_t)M_TOT * C_DIM];
__device__ __nv_bfloat16 g_xlo[(size_t)M_TOT * C_DIM];
__device__ __nv_bfloat16 g_ahi[(size_t)M_TOT * C_DIM];            // attn out hi
__device__ __nv_bfloat16 g_alo[(size_t)M_TOT * C_DIM];            // attn out lo
__device__ __nv_bfloat16 g_wqhi[QKV_N * C_DIM];
__device__ __nv_bfloat16 g_wqlo[QKV_N * C_DIM];
__device__ __nv_bfloat16 g_wphi[C_DIM * C_DIM];
__device__ __nv_bfloat16 g_wplo[C_DIM * C_DIM];

__device__ __forceinline__ uint32_t smem_u32(const void* p) {
    uint32_t a;
    asm("{ .reg .u64 t; cvta.to.shared.u64 t, %1; cvt.u32.u64 %0, t; }"
        : "=r"(a) : "l"(p));
    return a;
}
__device__ __forceinline__ uint32_t bfpack(__nv_bfloat16 a, __nv_bfloat16 b) {
    __nv_bfloat162 t = __halves2bfloat162(a, b);
    return reinterpret_cast<uint32_t&>(t);
}

#define LDSM_X4(r0, r1, r2, r3, addr) \
    asm volatile("ldmatrix.sync.aligned.m8n8.x4.shared.b16 {%0,%1,%2,%3}, [%4];" \
        : "=r"(r0), "=r"(r1), "=r"(r2), "=r"(r3) : "r"(addr))
#define LDSM_X2(r0, r1, addr) \
    asm volatile("ldmatrix.sync.aligned.m8n8.x2.shared.b16 {%0,%1}, [%2];" \
        : "=r"(r0), "=r"(r1) : "r"(addr))
#define MMA_BF16(c, a, b) \
    asm volatile("mma.sync.aligned.m16n8k16.row.col.f32.bf16.bf16.f32 " \
        "{%0,%1,%2,%3}, {%4,%5,%6,%7}, {%8,%9}, {%0,%1,%2,%3};" \
        : "+f"((c)[0]), "+f"((c)[1]), "+f"((c)[2]), "+f"((c)[3]) \
        : "r"((a)[0]), "r"((a)[1]), "r"((a)[2]), "r"((a)[3]), \
          "r"((b)[0]), "r"((b)[1]))

// ---------------------------------------------------------------------------
// fp32 -> bf16 hi/lo split
// ---------------------------------------------------------------------------
__global__ void split_kernel(const float* __restrict__ in,
                             __nv_bfloat16* __restrict__ hi,
                             __nv_bfloat16* __restrict__ lo, int n4)
{
    int i = blockIdx.x * blockDim.x + threadIdx.x;
    if (i >= n4) return;
    float4 v = ((const float4*)in)[i];
    float f[4] = {v.x, v.y, v.z, v.w};
    __nv_bfloat16 h[4], l[4];
    #pragma unroll
    for (int j = 0; j < 4; j++) {
        h[j] = __float2bfloat16(f[j]);
        l[j] = __float2bfloat16(f[j] - __bfloat162float(h[j]));
    }
    ((uint2*)hi)[i] = make_uint2(bfpack(h[0], h[1]), bfpack(h[2], h[3]));
    ((uint2*)lo)[i] = make_uint2(bfpack(l[0], l[1]), bfpack(l[2], l[3]));
}

// ---------------------------------------------------------------------------
// bias gather into [h][w][n][m]
// ---------------------------------------------------------------------------
__global__ void bias_gather_kernel(const float* __restrict__ table)
{
    int idx = blockIdx.x * blockDim.x + threadIdx.x;
    if (idx >= NTOK * NTOK) return;
    int m = idx % NTOK, n = idx / NTOK;
    int z1 = n / 72, h1 = (n / 12) % 6, w1 = n % 12;
    int z2 = m / 72, h2 = (m / 12) % 6, w2 = m % 12;
    int epi = (z1 + 2 * z2) * 828 + (h1 + 6 * h2) * 23 + (w1 - w2 + 11);
    const float* trow = table + (size_t)epi * (NWIN * NHEAD);
    #pragma unroll 4
    for (int wh = 0; wh < NWIN * NHEAD; wh++) {
        int w = wh / NHEAD, h = wh % NHEAD;
        g_bias[((size_t)(h * NWIN + w)) * (NTOK * NTOK) + idx] = trow[wh];
    }
}

// ---------------------------------------------------------------------------
// HMMA GEMM: C[M,N] = A[M,K] @ W[N,K]^T + bias[N], bf16 hi/lo 3-pass.
// CTA 128 threads, tile 128x64, K chunked 3x64 (padded smem rows of 72 bf16).
// Warp tile 64x32: 4x4 grid of m16n8k16 mma per k16-step.
// ---------------------------------------------------------------------------
#define SROW 72
#define OFF_AH 0
#define OFF_AL 18432
#define OFF_BH 36864
#define OFF_BL 46080
#define GEMM_SMEM 55296

__global__ __launch_bounds__(128, 3)
void hmma_gemm_kernel(const __nv_bfloat16* __restrict__ Ahi,
                      const __nv_bfloat16* __restrict__ Alo,
                      const __nv_bfloat16* __restrict__ Bhi,
                      const __nv_bfloat16* __restrict__ Blo,
                      const float* __restrict__ bias,
                      float* __restrict__ C, int ldc)
{
    extern __shared__ char smem[];
    const uint32_t sb = smem_u32(smem);
    const int tid = threadIdx.x, wid = tid >> 5, lane = tid & 31;
    const int wm = (wid >> 1) * 64;        // warp M offset in tile
    const int wn = (wid & 1) * 32;         // warp N offset in tile
    const int bm = blockIdx.y * 128;
    const int bn = blockIdx.x * 64;

    float acc[4][4][4];
    #pragma unroll
    for (int mi = 0; mi < 4; mi++)
        #pragma unroll
        for (int ni = 0; ni < 4; ni++)
            #pragma unroll
            for (int j = 0; j < 4; j++) acc[mi][ni][j] = 0.f;

    for (int kc = 0; kc < 3; kc++) {
        const int kb = kc * 64;
        // Load A chunk (128 rows x 64 bf16, hi+lo): 1024 uint4 each
        #pragma unroll
        for (int it = 0; it < 8; it++) {
            int i = tid + it * 128;
            int row = i >> 3, c8 = (i & 7) << 3;
            uint32_t so = (uint32_t)(row * SROW + c8) * 2;
            *(uint4*)(smem + OFF_AH + so) =
                *(const uint4*)(Ahi + (size_t)(bm + row) * KDIM + kb + c8);
            *(uint4*)(smem + OFF_AL + so) =
                *(const uint4*)(Alo + (size_t)(bm + row) * KDIM + kb + c8);
        }
        // Load B chunk (64 rows x 64 bf16, hi+lo): 512 uint4 each
        #pragma unroll
        for (int it = 0; it < 4; it++) {
            int i = tid + it * 128;
            int row = i >> 3, c8 = (i & 7) << 3;
            uint32_t so = (uint32_t)(row * SROW + c8) * 2;
            *(uint4*)(smem + OFF_BH + so) =
                *(const uint4*)(Bhi + (size_t)(bn + row) * KDIM + kb + c8);
            *(uint4*)(smem + OFF_BL + so) =
                *(const uint4*)(Blo + (size_t)(bn + row) * KDIM + kb + c8);
        }
        __syncthreads();

        #pragma unroll
        for (int ks = 0; ks < 4; ks++) {
            const int k0 = ks * 16;
            uint32_t ah[4][4], al[4][4], bh[4][2], bl[4][2];
            #pragma unroll
            for (int mi = 0; mi < 4; mi++) {
                uint32_t off = (uint32_t)((wm + mi * 16 + (lane & 15)) * SROW
                               + k0 + ((lane >> 4) << 3)) * 2;
                LDSM_X4(ah[mi][0], ah[mi][1], ah[mi][2], ah[mi][3],
                        sb + OFF_AH + off);
                LDSM_X4(al[mi][0], al[mi][1], al[mi][2], al[mi][3],
                        sb + OFF_AL + off);
            }
            #pragma unroll
            for (int ni = 0; ni < 4; ni++) {
                uint32_t off = (uint32_t)((wn + ni * 8 + (lane & 7)) * SROW
                               + k0 + (((lane >> 3) & 1) << 3)) * 2;
                LDSM_X2(bh[ni][0], bh[ni][1], sb + OFF_BH + off);
                LDSM_X2(bl[ni][0], bl[ni][1], sb + OFF_BL + off);
            }
            #pragma unroll
            for (int mi = 0; mi < 4; mi++)
                #pragma unroll
                for (int ni = 0; ni < 4; ni++) {
                    MMA_BF16(acc[mi][ni], ah[mi], bh[ni]);
                    MMA_BF16(acc[mi][ni], ah[mi], bl[ni]);
                    MMA_BF16(acc[mi][ni], al[mi], bh[ni]);
                }
        }
        __syncthreads();
    }

    // Epilogue: direct float2 stores + bias
    #pragma unroll
    for (int ni = 0; ni < 4; ni++) {
        const int col = bn + wn + ni * 8 + (lane & 3) * 2;
        const float2 bv = *(const float2*)(bias + col);
        #pragma unroll
        for (int mi = 0; mi < 4; mi++) {
            int r0 = bm + wm + mi * 16 + (lane >> 2);
            float2 o0, o1;
            o0.x = acc[mi][ni][0] + bv.x; o0.y = acc[mi][ni][1] + bv.y;
            o1.x = acc[mi][ni][2] + bv.x; o1.y = acc[mi][ni][3] + bv.y;
            *(float2*)(C + (size_t)r0 * ldc + col)       = o0;
            *(float2*)(C + (size_t)(r0 + 8) * ldc + col) = o1;
        }
    }
}

// ---------------------------------------------------------------------------
// Fused attention per (b_, h, w) block (576 threads). Emits bf16 hi/lo.
// ---------------------------------------------------------------------------
#define AT_THREADS 576
#define SPAD 148
#define ATTN_SMEM_FLOATS (NTOK * SPAD + 2 * 32 * SPAD + NTOK * 32 + NTOK)
#define ATTN_SMEM_BYTES  (ATTN_SMEM_FLOATS * 4)

__global__ __launch_bounds__(AT_THREADS, 1) void attn_kernel(
    const float* __restrict__ mask)
{
    const int w  = blockIdx.x & 63;
    const int hh = (blockIdx.x >> 6) % NHEAD;
    const int b_ = blockIdx.x / (NWIN * NHEAD);

    extern __shared__ float sm[];
    float* Ss    = sm;                       // [144][148]
    float* Qs    = Ss + NTOK * SPAD;         // [32][148]
    float* Ks    = Qs + 32 * SPAD;           // [32][148]
    float* Vs    = Ks + 32 * SPAD;           // [144][32]
    float* inv_s = Vs + NTOK * 32;           // [144]

    const int tid     = threadIdx.x;
    const int rowbase = (b_ * NWIN + w) * NTOK;

    #pragma unroll
    for (int it = 0; it < 2; it++) {
        int i  = tid + it * AT_THREADS;
        int n  = i >> 3;
        int l4 = (i & 7) << 2;
        const float* base = g_qkv + (size_t)(rowbase + n) * QKV_N + hh * LDIM;
        float4 q4 = *(const float4*)(base + l4);
        float4 k4 = *(const float4*)(base + 192 + l4);
        float4 v4 = *(const float4*)(base + 384 + l4);
        Qs[(l4 + 0) * SPAD + n] = q4.x; Qs[(l4 + 1) * SPAD + n] = q4.y;
        Qs[(l4 + 2) * SPAD + n] = q4.z; Qs[(l4 + 3) * SPAD + n] = q4.w;
        Ks[(l4 + 0) * SPAD + n] = k4.x; Ks[(l4 + 1) * SPAD + n] = k4.y;
        Ks[(l4 + 2) * SPAD + n] = k4.z; Ks[(l4 + 3) * SPAD + n] = k4.w;
        *(float4*)(Vs + n * 32 + l4) = v4;
    }
    __syncthreads();

    // GEMM1: 6x6 microtile, 24x24 grid
    {
        const int ty = tid / 24, tx = tid % 24;
        const int r0 = ty * 6,  c0 = tx * 6;
        float acc[6][6];
        #pragma unroll
        for (int i = 0; i < 6; i++)
            #pragma unroll
            for (int j = 0; j < 6; j++) acc[i][j] = 0.f;

        #pragma unroll 4
        for (int l = 0; l < 32; l++) {
            float a[6], b[6];
            const float2* ap = (const float2*)(Qs + l * SPAD + r0);
            const float2* bp = (const float2*)(Ks + l * SPAD + c0);
            float2 t;
            t = ap[0]; a[0] = t.x; a[1] = t.y;
            t = ap[1]; a[2] = t.x; a[3] = t.y;
            t = ap[2]; a[4] = t.x; a[5] = t.y;
            t = bp[0]; b[0] = t.x; b[1] = t.y;
            t = bp[1]; b[2] = t.x; b[3] = t.y;
            t = bp[2]; b[4] = t.x; b[5] = t.y;
            #pragma unroll
            for (int i = 0; i < 6; i++)
                #pragma unroll
                for (int j = 0; j < 6; j++) acc[i][j] += a[i] * b[j];
        }
        const float scale = 0.17677669529663687f;
        #pragma unroll
        for (int i = 0; i < 6; i++)
            #pragma unroll
            for (int j = 0; j < 6; j++)
                Ss[(r0 + i) * SPAD + c0 + j] = acc[i][j] * scale;
    }
    __syncthreads();

    // bias + mask
    {
        const float* bslab = g_bias + (size_t)(hh * NWIN + w) * (NTOK * NTOK);
        const float* mslab = mask   + (size_t)(b_ * NWIN + w) * (NTOK * NTOK);
        #pragma unroll 4
        for (int it = 0; it < 36; it++) {
            int i = tid + it * AT_THREADS;
            int n = i / NTOK;
            int m = i - n * NTOK;
            Ss[n * SPAD + m] += bslab[i] + mslab[i];
        }
    }
    __syncthreads();

    // softmax: 4 threads/row
    {
        const int r = tid >> 2, q = tid & 3;
        float* row = Ss + r * SPAD + q * 36;
        float mx = -1e30f;
        #pragma unroll 4
        for (int c = 0; c < 36; c++) mx = fmaxf(mx, row[c]);
        mx = fmaxf(mx, __shfl_xor_sync(0xffffffffu, mx, 1));
        mx = fmaxf(mx, __shfl_xor_sync(0xffffffffu, mx, 2));
        float sum = 0.f;
        #pragma unroll 4
        for (int c = 0; c < 36; c++) {
            float e = __expf(row[c] - mx);
            row[c] = e;
            sum += e;
        }
        sum += __shfl_xor_sync(0xffffffffu, sum, 1);
        sum += __shfl_xor_sync(0xffffffffu, sum, 2);
        if (q == 0) inv_s[r] = 1.0f / sum;
    }
    __syncthreads();

    // GEMM2 + bf16 hi/lo epilogue
    {
        const int r  = tid >> 2;
        const int l0 = (tid & 3) << 3;
        float acc2[8];
        #pragma unroll
        for (int j = 0; j < 8; j++) acc2[j] = 0.f;

        const float* srow = Ss + r * SPAD;
        #pragma unroll 4
        for (int m = 0; m < NTOK; m++) {
            float4 v0 = *(const float4*)(Vs + m * 32 + l0);
            float4 v1 = *(const float4*)(Vs + m * 32 + l0 + 4);
            float p = srow[m];
            acc2[0] += p * v0.x; acc2[1] += p * v0.y;
            acc2[2] += p * v0.z; acc2[3] += p * v0.w;
            acc2[4] += p * v1.x; acc2[5] += p * v1.y;
            acc2[6] += p * v1.z; acc2[7] += p * v1.w;
        }
        const float inv = inv_s[r];
        uint32_t hu[4], lu[4];
        #pragma unroll
        for (int j = 0; j < 4; j++) {
            float v0 = acc2[2 * j]     * inv;
            float v1 = acc2[2 * j + 1] * inv;
            __nv_bfloat16 h0 = __float2bfloat16(v0);
            __nv_bfloat16 h1 = __float2bfloat16(v1);
            __nv_bfloat16 l0b = __float2bfloat16(v0 - __bfloat162float(h0));
            __nv_bfloat16 l1b = __float2bfloat16(v1 - __bfloat162float(h1));
            hu[j] = bfpack(h0, h1);
            lu[j] = bfpack(l0b, l1b);
        }
        size_t oidx = (size_t)(rowbase + r) * C_DIM + hh * LDIM + l0;
        *(uint4*)(g_ahi + oidx) = make_uint4(hu[0], hu[1], hu[2], hu[3]);
        *(uint4*)(g_alo + oidx) = make_uint4(lu[0], lu[1], lu[2], lu[3]);
    }
}

// ---------------------------------------------------------------------------
// Launch
// ---------------------------------------------------------------------------
extern "C" void kernel_launch(void* const* d_in, const int* in_sizes, int n_in,
                              void* d_out, int out_size)
{
    const float* x      = (const float*)d_in[0];
    const float* mask   = (const float*)d_in[1];
    const float* qkv_w  = (const float*)d_in[2];
    const float* qkv_b  = (const float*)d_in[3];
    const float* proj_w = (const float*)d_in[4];
    const float* proj_b = (const float*)d_in[5];
    const float* btab   = (const float*)d_in[6];
    float* out = (float*)d_out;

    float* qkv_p;
    __nv_bfloat16 *xhi, *xlo, *ahi, *alo, *wqhi, *wqlo, *wphi, *wplo;
    cudaGetSymbolAddress((void**)&qkv_p, g_qkv);
    cudaGetSymbolAddress((void**)&xhi, g_xhi);
    cudaGetSymbolAddress((void**)&xlo, g_xlo);
    cudaGetSymbolAddress((void**)&ahi, g_ahi);
    cudaGetSymbolAddress((void**)&alo, g_alo);
    cudaGetSymbolAddress((void**)&wqhi, g_wqhi);
    cudaGetSymbolAddress((void**)&wqlo, g_wqlo);
    cudaGetSymbolAddress((void**)&wphi, g_wphi);
    cudaGetSymbolAddress((void**)&wplo, g_wplo);

    cudaFuncSetAttribute(attn_kernel,
                         cudaFuncAttributeMaxDynamicSharedMemorySize,
                         ATTN_SMEM_BYTES);
    cudaFuncSetAttribute(hmma_gemm_kernel,
                         cudaFuncAttributeMaxDynamicSharedMemorySize,
                         GEMM_SMEM);

    // 1) bf16 hi/lo splits
    {
        int n4 = (M_TOT * C_DIM) / 4;
        split_kernel<<<(n4 + 255) / 256, 256>>>(x, xhi, xlo, n4);
        int w4 = (QKV_N * C_DIM) / 4;
        split_kernel<<<(w4 + 255) / 256, 256>>>(qkv_w, wqhi, wqlo, w4);
        int p4 = (C_DIM * C_DIM) / 4;
        split_kernel<<<(p4 + 255) / 256, 256>>>(proj_w, wphi, wplo, p4);
    }

    // 2) bias gather
    bias_gather_kernel<<<(NTOK * NTOK + 255) / 256, 256>>>(btab);

    // 3) QKV projection (HMMA): [138240,192] @ [576,192]^T + b
    hmma_gemm_kernel<<<dim3(QKV_N / 64, M_TOT / 128), 128, GEMM_SMEM>>>(
        xhi, xlo, wqhi, wqlo, qkv_b, qkv_p, QKV_N);

    // 4) fused attention (emits bf16 hi/lo)
    attn_kernel<<<NB * NHEAD * NWIN, AT_THREADS, ATTN_SMEM_BYTES>>>(mask);

    // 5) output projection (HMMA): [138240,192] @ [192,192]^T + b
    hmma_gemm_kernel<<<dim3(C_DIM / 64, M_TOT / 128), 128, GEMM_SMEM>>>(
        ahi, alo, wphi, wplo, proj_b, out, C_DIM);
}